// round 1
// baseline (speedup 1.0000x reference)
#include <cuda_runtime.h>
#include <cuda_bf16.h>
#include <cstdint>

#define TT 2048
#define BB 32
#define NN 1024
#define QQ 512

// -------- scratch (device globals; no allocations allowed) --------
__device__ __nv_bfloat16 g_Abf[(size_t)TT * BB * NN];   // hyp in bf16, rows m=t*B+b
__device__ __nv_bfloat16 g_Wbf[QQ * NN];                // W_w in bf16 (row-major [q][k])
__device__ float g_msum[BB * NN];                       // sum over T (scaled later)
__device__ float g_gvec[BB * QQ];                       // g[b,q] = Wh[q]*tanh(m@Wm^T+bm)
__device__ float g_score[BB * TT];                      // scores, then attn weights

__device__ __forceinline__ float fast_tanh(float x) {
    float y;
    asm("tanh.approx.f32 %0, %1;" : "=f"(y) : "f"(x));
    return y;
}

// -------- zero scratch + output (d_out is poisoned) --------
__global__ void k_zero(float* __restrict__ out) {
    int i = blockIdx.x * 256 + threadIdx.x;   // grid covers 65536
    if (i < BB * NN) { g_msum[i] = 0.f; out[i] = 0.f; }
    g_score[i] = 0.f;
}

// -------- convert W_w to bf16 --------
__global__ void k_convW(const float* __restrict__ W) {
    int i = blockIdx.x * 256 + threadIdx.x;
    g_Wbf[i] = __float2bfloat16(W[i]);
}

// -------- mean over T (partials via atomics) + bf16 conversion of hyp --------
__global__ void k_mean(const float* __restrict__ hyp) {
    int b   = blockIdx.x;
    int tc  = blockIdx.y;      // 16 chunks of 128 timesteps
    int tid = threadIdx.x;     // 256 threads * 4 floats = 1024 = NN
    float a0 = 0.f, a1 = 0.f, a2 = 0.f, a3 = 0.f;
    size_t base = ((size_t)tc * 128 * BB + b) * NN + (size_t)tid * 4;
    #pragma unroll 4
    for (int t = 0; t < 128; t++) {
        size_t off = base + (size_t)t * BB * NN;
        float4 v = *(const float4*)(hyp + off);
        a0 += v.x; a1 += v.y; a2 += v.z; a3 += v.w;
        __nv_bfloat162 lo = __floats2bfloat162_rn(v.x, v.y);
        __nv_bfloat162 hi = __floats2bfloat162_rn(v.z, v.w);
        uint2 u;
        u.x = *(uint32_t*)&lo;
        u.y = *(uint32_t*)&hi;
        *(uint2*)(g_Abf + off) = u;
    }
    int n0 = tid * 4;
    atomicAdd(&g_msum[b * NN + n0 + 0], a0);
    atomicAdd(&g_msum[b * NN + n0 + 1], a1);
    atomicAdd(&g_msum[b * NN + n0 + 2], a2);
    atomicAdd(&g_msum[b * NN + n0 + 3], a3);
}

// -------- g[b,q] = Wh_w[q] * tanh(mean . Wm_w[q] + Wm_b[q]) --------
__global__ void k_g(const float* __restrict__ Wm_w, const float* __restrict__ Wm_b,
                    const float* __restrict__ Wh_w) {
    int b = blockIdx.x;
    int k = threadIdx.x;       // 512 threads, one q each
    __shared__ float m[NN];
    for (int i = k; i < NN; i += 512) m[i] = g_msum[b * NN + i] * (1.0f / (float)TT);
    __syncthreads();
    const float* w = Wm_w + (size_t)k * NN;
    float acc = 0.f;
    #pragma unroll 8
    for (int i = 0; i < NN; i++) acc = fmaf(m[i], w[i], acc);
    g_gvec[b * QQ + k] = tanhf(acc + Wm_b[k]) * Wh_w[k];
}

// -------- big GEMM (bf16 mma.sync) + fused tanh/score epilogue --------
#define BM 128
#define BQ 128
#define BK 32
#define LDT 40   // row stride in bf16 elems (80B) -> conflict-free fragment LDS

__global__ void __launch_bounds__(256) k_gemm(const float* __restrict__ Wbias) {
    __shared__ __align__(16) __nv_bfloat16 As[BM * LDT];
    __shared__ __align__(16) __nv_bfloat16 Bs[BQ * LDT];
    __shared__ float gsm[BB * 128];
    __shared__ float bsm[128];

    const int qc  = blockIdx.x;   // 0..3 : 128-wide chunk of N2
    const int mt  = blockIdx.y;   // 0..511 : 128-row tile of M=65536
    const int tid = threadIdx.x;
    const int warp = tid >> 5, lane = tid & 31;
    const int wm = (warp >> 1) * 32;   // warp row offset (4 groups of 32)
    const int wq = (warp & 1) * 64;    // warp col offset (2 groups of 64)

    // stage g[b, q] and bias for this q-chunk
    for (int i = tid; i < BB * 128; i += 256)
        gsm[i] = g_gvec[(i >> 7) * QQ + qc * 128 + (i & 127)];
    if (tid < 128) bsm[tid] = Wbias[qc * 128 + tid];

    float acc[2][8][4];
    #pragma unroll
    for (int i = 0; i < 2; i++)
        #pragma unroll
        for (int j = 0; j < 8; j++)
            #pragma unroll
            for (int e = 0; e < 4; e++) acc[i][j][e] = 0.f;

    const __nv_bfloat16* Ab = g_Abf + (size_t)mt * 128 * NN;
    const __nv_bfloat16* Bb = g_Wbf + (size_t)qc * 128 * NN;

    const int lr = tid >> 2;        // 0..63 : tile row for loads
    const int lc = (tid & 3) * 8;   // 0,8,16,24 : bf16 col offset (16B)

    for (int kb = 0; kb < NN; kb += BK) {
        __syncthreads();
        #pragma unroll
        for (int p = 0; p < 2; p++) {
            int r = p * 64 + lr;
            *(uint4*)&As[r * LDT + lc] = *(const uint4*)(Ab + (size_t)r * NN + kb + lc);
            *(uint4*)&Bs[r * LDT + lc] = *(const uint4*)(Bb + (size_t)r * NN + kb + lc);
        }
        __syncthreads();
        #pragma unroll
        for (int ks = 0; ks < 2; ks++) {
            int c = ks * 16 + (lane & 3) * 2;
            uint32_t a[2][4];
            #pragma unroll
            for (int i = 0; i < 2; i++) {
                int r = wm + i * 16 + (lane >> 2);
                a[i][0] = *(const uint32_t*)&As[r * LDT + c];
                a[i][1] = *(const uint32_t*)&As[(r + 8) * LDT + c];
                a[i][2] = *(const uint32_t*)&As[r * LDT + c + 8];
                a[i][3] = *(const uint32_t*)&As[(r + 8) * LDT + c + 8];
            }
            #pragma unroll
            for (int j = 0; j < 8; j++) {
                int q = wq + j * 8 + (lane >> 2);
                uint32_t b0 = *(const uint32_t*)&Bs[q * LDT + c];
                uint32_t b1 = *(const uint32_t*)&Bs[q * LDT + c + 8];
                #pragma unroll
                for (int i = 0; i < 2; i++) {
                    asm volatile(
                        "mma.sync.aligned.m16n8k16.row.col.f32.bf16.bf16.f32 "
                        "{%0,%1,%2,%3}, {%4,%5,%6,%7}, {%8,%9}, {%0,%1,%2,%3};\n"
                        : "+f"(acc[i][j][0]), "+f"(acc[i][j][1]),
                          "+f"(acc[i][j][2]), "+f"(acc[i][j][3])
                        : "r"(a[i][0]), "r"(a[i][1]), "r"(a[i][2]), "r"(a[i][3]),
                          "r"(b0), "r"(b1));
                }
            }
        }
    }

    // epilogue: score_partial[m] = sum_q tanh(z + bias) * g[b, q]
    int bidx[2][2], trow[2][2];
    #pragma unroll
    for (int i = 0; i < 2; i++)
        #pragma unroll
        for (int h = 0; h < 2; h++) {
            int m = mt * 128 + wm + i * 16 + h * 8 + (lane >> 2);
            bidx[i][h] = m & (BB - 1);   // b = m % 32
            trow[i][h] = m >> 5;         // t = m / 32
        }
    float rs[2][2] = {{0.f, 0.f}, {0.f, 0.f}};
    #pragma unroll
    for (int i = 0; i < 2; i++)
        #pragma unroll
        for (int j = 0; j < 8; j++) {
            int ql = wq + j * 8 + ((lane & 3) << 1);
            float bb0 = bsm[ql], bb1 = bsm[ql + 1];
            #pragma unroll
            for (int h = 0; h < 2; h++) {
                float t0 = fast_tanh(acc[i][j][2 * h + 0] + bb0);
                float t1 = fast_tanh(acc[i][j][2 * h + 1] + bb1);
                const float* gp = &gsm[(bidx[i][h] << 7) + ql];
                rs[i][h] += t0 * gp[0] + t1 * gp[1];
            }
        }
    #pragma unroll
    for (int i = 0; i < 2; i++)
        #pragma unroll
        for (int h = 0; h < 2; h++) {
            float v = rs[i][h];
            v += __shfl_xor_sync(0xffffffffu, v, 1);
            v += __shfl_xor_sync(0xffffffffu, v, 2);
            if ((lane & 3) == 0)
                atomicAdd(&g_score[bidx[i][h] * TT + trow[i][h]], v);
        }
}

// -------- softmax over T per b (in-place on g_score) --------
__global__ void k_softmax() {
    int b = blockIdx.x, tid = threadIdx.x;  // 256 threads
    __shared__ float sh[TT];
    __shared__ float red[8];
    __shared__ float bcast;
    float mx = -1e30f;
    for (int i = tid; i < TT; i += 256) {
        float v = g_score[b * TT + i];
        sh[i] = v;
        mx = fmaxf(mx, v);
    }
    #pragma unroll
    for (int o = 16; o > 0; o >>= 1) mx = fmaxf(mx, __shfl_xor_sync(0xffffffffu, mx, o));
    if ((tid & 31) == 0) red[tid >> 5] = mx;
    __syncthreads();
    if (tid == 0) {
        float m2 = red[0];
        for (int i = 1; i < 8; i++) m2 = fmaxf(m2, red[i]);
        bcast = m2;
    }
    __syncthreads();
    mx = bcast;
    float s = 0.f;
    for (int i = tid; i < TT; i += 256) {
        float e = __expf(sh[i] - mx);
        sh[i] = e;
        s += e;
    }
    #pragma unroll
    for (int o = 16; o > 0; o >>= 1) s += __shfl_xor_sync(0xffffffffu, s, o);
    if ((tid & 31) == 0) red[tid >> 5] = s;
    __syncthreads();
    if (tid == 0) {
        float t = 0.f;
        for (int i = 0; i < 8; i++) t += red[i];
        bcast = 1.f / t;
    }
    __syncthreads();
    float inv = bcast;
    for (int i = tid; i < TT; i += 256) g_score[b * TT + i] = sh[i] * inv;
}

// -------- c[b,n] = sum_t a[b,t] * hyp[t,b,n] (partials via atomics) --------
__global__ void k_wsum(const float* __restrict__ hyp, float* __restrict__ out) {
    int b = blockIdx.x, tc = blockIdx.y, tid = threadIdx.x;
    __shared__ float aw[128];
    if (tid < 128) aw[tid] = g_score[b * TT + tc * 128 + tid];
    __syncthreads();
    float a0 = 0.f, a1 = 0.f, a2 = 0.f, a3 = 0.f;
    size_t base = ((size_t)tc * 128 * BB + b) * NN + (size_t)tid * 4;
    #pragma unroll 4
    for (int t = 0; t < 128; t++) {
        float w = aw[t];
        float4 v = *(const float4*)(hyp + base + (size_t)t * BB * NN);
        a0 = fmaf(w, v.x, a0);
        a1 = fmaf(w, v.y, a1);
        a2 = fmaf(w, v.z, a2);
        a3 = fmaf(w, v.w, a3);
    }
    int n0 = tid * 4;
    atomicAdd(&out[b * NN + n0 + 0], a0);
    atomicAdd(&out[b * NN + n0 + 1], a1);
    atomicAdd(&out[b * NN + n0 + 2], a2);
    atomicAdd(&out[b * NN + n0 + 3], a3);
}

extern "C" void kernel_launch(void* const* d_in, const int* in_sizes, int n_in,
                              void* d_out, int out_size) {
    (void)in_sizes; (void)n_in; (void)out_size;
    const float* hyp  = (const float*)d_in[0];
    const float* W_w  = (const float*)d_in[1];
    const float* W_b  = (const float*)d_in[2];
    const float* Wm_w = (const float*)d_in[3];
    const float* Wm_b = (const float*)d_in[4];
    const float* Wh_w = (const float*)d_in[5];
    // d_in[6] = Wh_b: softmax-invariant constant, intentionally unused.
    float* out = (float*)d_out;

    k_zero<<<(BB * TT) / 256, 256>>>(out);
    k_convW<<<(QQ * NN) / 256, 256>>>(W_w);
    k_mean<<<dim3(BB, 16), 256>>>(hyp);
    k_g<<<BB, 512>>>(Wm_w, Wm_b, Wh_w);
    k_gemm<<<dim3(4, 512), 256>>>(W_b);
    k_softmax<<<BB, 256>>>();
    k_wsum<<<dim3(BB, 16), 256>>>(hyp, out);
}

// round 2
// speedup vs baseline: 1.1168x; 1.1168x over previous
#include <cuda_runtime.h>
#include <cuda_bf16.h>
#include <cstdint>

#define TT 2048
#define BB 32
#define NN 1024
#define QQ 512

// -------- scratch (device globals; no allocations allowed) --------
__device__ __nv_bfloat16 g_Abf[(size_t)TT * BB * NN];   // hyp in bf16, rows m=t*B+b
__device__ __nv_bfloat16 g_Wbf[QQ * NN];                // W_w in bf16 (row-major [q][k])
__device__ float g_msum[BB * NN];                       // sum over T (scaled later)
__device__ float g_gvec[BB * QQ];                       // g[b,q] = Wh[q]*tanh(m@Wm^T+bm)
__device__ float g_score[BB * TT];                      // scores, then attn weights

__device__ __forceinline__ float fast_tanh(float x) {
    float y;
    asm("tanh.approx.f32 %0, %1;" : "=f"(y) : "f"(x));
    return y;
}

// -------- zero scratch + output (d_out is poisoned) --------
__global__ void k_zero(float* __restrict__ out) {
    int i = blockIdx.x * 256 + threadIdx.x;   // grid covers 65536
    if (i < BB * NN) { g_msum[i] = 0.f; out[i] = 0.f; }
    g_score[i] = 0.f;
}

// -------- convert W_w to bf16 --------
__global__ void k_convW(const float* __restrict__ W) {
    int i = blockIdx.x * 256 + threadIdx.x;
    g_Wbf[i] = __float2bfloat16(W[i]);
}

// -------- mean over T (partials via atomics) + bf16 conversion of hyp --------
__global__ void k_mean(const float* __restrict__ hyp) {
    int b   = blockIdx.x;
    int tc  = blockIdx.y;      // 16 chunks of 128 timesteps
    int tid = threadIdx.x;     // 256 threads * 4 floats = 1024 = NN
    float a0 = 0.f, a1 = 0.f, a2 = 0.f, a3 = 0.f;
    size_t base = ((size_t)tc * 128 * BB + b) * NN + (size_t)tid * 4;
    #pragma unroll 4
    for (int t = 0; t < 128; t++) {
        size_t off = base + (size_t)t * BB * NN;
        float4 v = *(const float4*)(hyp + off);
        a0 += v.x; a1 += v.y; a2 += v.z; a3 += v.w;
        __nv_bfloat162 lo = __floats2bfloat162_rn(v.x, v.y);
        __nv_bfloat162 hi = __floats2bfloat162_rn(v.z, v.w);
        uint2 u;
        u.x = *(uint32_t*)&lo;
        u.y = *(uint32_t*)&hi;
        *(uint2*)(g_Abf + off) = u;
    }
    int n0 = tid * 4;
    atomicAdd(&g_msum[b * NN + n0 + 0], a0);
    atomicAdd(&g_msum[b * NN + n0 + 1], a1);
    atomicAdd(&g_msum[b * NN + n0 + 2], a2);
    atomicAdd(&g_msum[b * NN + n0 + 3], a3);
}

// -------- g[b,q] = Wh_w[q] * tanh(mean . Wm_w[q] + Wm_b[q]) --------
// One warp per (b, q) dot product. grid = (QQ/8, BB), 8 warps/CTA.
__global__ void __launch_bounds__(256) k_g(const float* __restrict__ Wm_w,
                                           const float* __restrict__ Wm_b,
                                           const float* __restrict__ Wh_w) {
    const int b    = blockIdx.y;
    const int tid  = threadIdx.x;
    const int warp = tid >> 5, lane = tid & 31;
    const int q    = blockIdx.x * 8 + warp;

    __shared__ __align__(16) float m[NN];
    for (int i = tid; i < NN / 4; i += 256) {
        float4 v = *(const float4*)(g_msum + b * NN + i * 4);
        v.x *= (1.0f / (float)TT); v.y *= (1.0f / (float)TT);
        v.z *= (1.0f / (float)TT); v.w *= (1.0f / (float)TT);
        *(float4*)(m + i * 4) = v;
    }
    __syncthreads();

    const float4* w4 = (const float4*)(Wm_w + (size_t)q * NN);
    const float4* m4 = (const float4*)m;
    float a0 = 0.f, a1 = 0.f, a2 = 0.f, a3 = 0.f;
    #pragma unroll
    for (int j = 0; j < 8; j++) {
        float4 wv = w4[lane + 32 * j];   // coalesced across lanes
        float4 mv = m4[lane + 32 * j];
        a0 = fmaf(mv.x, wv.x, a0);
        a1 = fmaf(mv.y, wv.y, a1);
        a2 = fmaf(mv.z, wv.z, a2);
        a3 = fmaf(mv.w, wv.w, a3);
    }
    float acc = (a0 + a1) + (a2 + a3);
    #pragma unroll
    for (int o = 16; o > 0; o >>= 1) acc += __shfl_xor_sync(0xffffffffu, acc, o);
    if (lane == 0)
        g_gvec[b * QQ + q] = tanhf(acc + Wm_b[q]) * Wh_w[q];
}

// -------- big GEMM (bf16 mma.sync) + fused tanh/score epilogue --------
#define BM 128
#define BQ 128
#define BK 32
#define LDT 40   // row stride in bf16 elems (80B) -> conflict-free fragment LDS

__global__ void __launch_bounds__(256) k_gemm(const float* __restrict__ Wbias) {
    __shared__ __align__(16) __nv_bfloat16 As[BM * LDT];
    __shared__ __align__(16) __nv_bfloat16 Bs[BQ * LDT];
    __shared__ float gsm[BB * 128];
    __shared__ float bsm[128];

    const int qc  = blockIdx.x;   // 0..3 : 128-wide chunk of N2
    const int mt  = blockIdx.y;   // 0..511 : 128-row tile of M=65536
    const int tid = threadIdx.x;
    const int warp = tid >> 5, lane = tid & 31;
    const int wm = (warp >> 1) * 32;   // warp row offset (4 groups of 32)
    const int wq = (warp & 1) * 64;    // warp col offset (2 groups of 64)

    // stage g[b, q] and bias for this q-chunk
    for (int i = tid; i < BB * 128; i += 256)
        gsm[i] = g_gvec[(i >> 7) * QQ + qc * 128 + (i & 127)];
    if (tid < 128) bsm[tid] = Wbias[qc * 128 + tid];

    float acc[2][8][4];
    #pragma unroll
    for (int i = 0; i < 2; i++)
        #pragma unroll
        for (int j = 0; j < 8; j++)
            #pragma unroll
            for (int e = 0; e < 4; e++) acc[i][j][e] = 0.f;

    const __nv_bfloat16* Ab = g_Abf + (size_t)mt * 128 * NN;
    const __nv_bfloat16* Bb = g_Wbf + (size_t)qc * 128 * NN;

    const int lr = tid >> 2;        // 0..63 : tile row for loads
    const int lc = (tid & 3) * 8;   // 0,8,16,24 : bf16 col offset (16B)

    for (int kb = 0; kb < NN; kb += BK) {
        __syncthreads();
        #pragma unroll
        for (int p = 0; p < 2; p++) {
            int r = p * 64 + lr;
            *(uint4*)&As[r * LDT + lc] = *(const uint4*)(Ab + (size_t)r * NN + kb + lc);
            *(uint4*)&Bs[r * LDT + lc] = *(const uint4*)(Bb + (size_t)r * NN + kb + lc);
        }
        __syncthreads();
        #pragma unroll
        for (int ks = 0; ks < 2; ks++) {
            int c = ks * 16 + (lane & 3) * 2;
            uint32_t a[2][4];
            #pragma unroll
            for (int i = 0; i < 2; i++) {
                int r = wm + i * 16 + (lane >> 2);
                a[i][0] = *(const uint32_t*)&As[r * LDT + c];
                a[i][1] = *(const uint32_t*)&As[(r + 8) * LDT + c];
                a[i][2] = *(const uint32_t*)&As[r * LDT + c + 8];
                a[i][3] = *(const uint32_t*)&As[(r + 8) * LDT + c + 8];
            }
            #pragma unroll
            for (int j = 0; j < 8; j++) {
                int q = wq + j * 8 + (lane >> 2);
                uint32_t b0 = *(const uint32_t*)&Bs[q * LDT + c];
                uint32_t b1 = *(const uint32_t*)&Bs[q * LDT + c + 8];
                #pragma unroll
                for (int i = 0; i < 2; i++) {
                    asm volatile(
                        "mma.sync.aligned.m16n8k16.row.col.f32.bf16.bf16.f32 "
                        "{%0,%1,%2,%3}, {%4,%5,%6,%7}, {%8,%9}, {%0,%1,%2,%3};\n"
                        : "+f"(acc[i][j][0]), "+f"(acc[i][j][1]),
                          "+f"(acc[i][j][2]), "+f"(acc[i][j][3])
                        : "r"(a[i][0]), "r"(a[i][1]), "r"(a[i][2]), "r"(a[i][3]),
                          "r"(b0), "r"(b1));
                }
            }
        }
    }

    // epilogue: score_partial[m] = sum_q tanh(z + bias) * g[b, q]
    int bidx[2][2], trow[2][2];
    #pragma unroll
    for (int i = 0; i < 2; i++)
        #pragma unroll
        for (int h = 0; h < 2; h++) {
            int m = mt * 128 + wm + i * 16 + h * 8 + (lane >> 2);
            bidx[i][h] = m & (BB - 1);   // b = m % 32
            trow[i][h] = m >> 5;         // t = m / 32
        }
    float rs[2][2] = {{0.f, 0.f}, {0.f, 0.f}};
    #pragma unroll
    for (int i = 0; i < 2; i++)
        #pragma unroll
        for (int j = 0; j < 8; j++) {
            int ql = wq + j * 8 + ((lane & 3) << 1);
            float bb0 = bsm[ql], bb1 = bsm[ql + 1];
            #pragma unroll
            for (int h = 0; h < 2; h++) {
                float t0 = fast_tanh(acc[i][j][2 * h + 0] + bb0);
                float t1 = fast_tanh(acc[i][j][2 * h + 1] + bb1);
                const float* gp = &gsm[(bidx[i][h] << 7) + ql];
                rs[i][h] += t0 * gp[0] + t1 * gp[1];
            }
        }
    #pragma unroll
    for (int i = 0; i < 2; i++)
        #pragma unroll
        for (int h = 0; h < 2; h++) {
            float v = rs[i][h];
            v += __shfl_xor_sync(0xffffffffu, v, 1);
            v += __shfl_xor_sync(0xffffffffu, v, 2);
            if ((lane & 3) == 0)
                atomicAdd(&g_score[bidx[i][h] * TT + trow[i][h]], v);
        }
}

// -------- softmax over T per b (in-place on g_score) --------
__global__ void k_softmax() {
    int b = blockIdx.x, tid = threadIdx.x;  // 256 threads
    __shared__ float sh[TT];
    __shared__ float red[8];
    __shared__ float bcast;
    float mx = -1e30f;
    for (int i = tid; i < TT; i += 256) {
        float v = g_score[b * TT + i];
        sh[i] = v;
        mx = fmaxf(mx, v);
    }
    #pragma unroll
    for (int o = 16; o > 0; o >>= 1) mx = fmaxf(mx, __shfl_xor_sync(0xffffffffu, mx, o));
    if ((tid & 31) == 0) red[tid >> 5] = mx;
    __syncthreads();
    if (tid == 0) {
        float m2 = red[0];
        for (int i = 1; i < 8; i++) m2 = fmaxf(m2, red[i]);
        bcast = m2;
    }
    __syncthreads();
    mx = bcast;
    float s = 0.f;
    for (int i = tid; i < TT; i += 256) {
        float e = __expf(sh[i] - mx);
        sh[i] = e;
        s += e;
    }
    #pragma unroll
    for (int o = 16; o > 0; o >>= 1) s += __shfl_xor_sync(0xffffffffu, s, o);
    if ((tid & 31) == 0) red[tid >> 5] = s;
    __syncthreads();
    if (tid == 0) {
        float t = 0.f;
        for (int i = 0; i < 8; i++) t += red[i];
        bcast = 1.f / t;
    }
    __syncthreads();
    float inv = bcast;
    for (int i = tid; i < TT; i += 256) g_score[b * TT + i] = sh[i] * inv;
}

// -------- c[b,n] = sum_t a[b,t] * hyp[t,b,n] (partials via atomics) --------
__global__ void k_wsum(const float* __restrict__ hyp, float* __restrict__ out) {
    int b = blockIdx.x, tc = blockIdx.y, tid = threadIdx.x;
    __shared__ float aw[128];
    if (tid < 128) aw[tid] = g_score[b * TT + tc * 128 + tid];
    __syncthreads();
    float a0 = 0.f, a1 = 0.f, a2 = 0.f, a3 = 0.f;
    size_t base = ((size_t)tc * 128 * BB + b) * NN + (size_t)tid * 4;
    #pragma unroll 4
    for (int t = 0; t < 128; t++) {
        float w = aw[t];
        float4 v = *(const float4*)(hyp + base + (size_t)t * BB * NN);
        a0 = fmaf(w, v.x, a0);
        a1 = fmaf(w, v.y, a1);
        a2 = fmaf(w, v.z, a2);
        a3 = fmaf(w, v.w, a3);
    }
    int n0 = tid * 4;
    atomicAdd(&out[b * NN + n0 + 0], a0);
    atomicAdd(&out[b * NN + n0 + 1], a1);
    atomicAdd(&out[b * NN + n0 + 2], a2);
    atomicAdd(&out[b * NN + n0 + 3], a3);
}

extern "C" void kernel_launch(void* const* d_in, const int* in_sizes, int n_in,
                              void* d_out, int out_size) {
    (void)in_sizes; (void)n_in; (void)out_size;
    const float* hyp  = (const float*)d_in[0];
    const float* W_w  = (const float*)d_in[1];
    const float* W_b  = (const float*)d_in[2];
    const float* Wm_w = (const float*)d_in[3];
    const float* Wm_b = (const float*)d_in[4];
    const float* Wh_w = (const float*)d_in[5];
    // d_in[6] = Wh_b: softmax-invariant constant, intentionally unused.
    float* out = (float*)d_out;

    k_zero<<<(BB * TT) / 256, 256>>>(out);
    k_convW<<<(QQ * NN) / 256, 256>>>(W_w);
    k_mean<<<dim3(BB, 16), 256>>>(hyp);
    k_g<<<dim3(QQ / 8, BB), 256>>>(Wm_w, Wm_b, Wh_w);
    k_gemm<<<dim3(4, 512), 256>>>(W_b);
    k_softmax<<<BB, 256>>>();
    k_wsum<<<dim3(BB, 16), 256>>>(hyp, out);
}

// round 5
// speedup vs baseline: 1.6883x; 1.5117x over previous
#include <cuda_runtime.h>
#include <cuda_bf16.h>
#include <cstdint>

#define TT 2048
#define BB 32
#define NN 1024
#define QQ 512

// -------- scratch (device globals; no allocations allowed) --------
__device__ __nv_bfloat16 g_Abf[(size_t)TT * BB * NN];   // hyp in bf16, rows m=t*B+b
__device__ __nv_bfloat16 g_Wbf[QQ * NN];                // W_w in bf16 (row-major [q][k])
__device__ float g_msum[BB * NN];                       // sum over T (scaled later)
__device__ float g_gvec[BB * QQ];                       // g[b,q] = Wh[q]*tanh(m@Wm^T+bm)
__device__ float g_score[BB * TT];                      // scores, then attn weights

__device__ __forceinline__ float fast_tanh(float x) {
    float y;
    asm("tanh.approx.f32 %0, %1;" : "=f"(y) : "f"(x));
    return y;
}

__device__ __forceinline__ uint32_t smem_u32(const void* p) {
    uint32_t a;
    asm("{ .reg .u64 t; cvta.to.shared.u64 t, %1; cvt.u32.u64 %0, t; }" : "=r"(a) : "l"(p));
    return a;
}
#define CP_ASYNC16(dst, src) \
    asm volatile("cp.async.cg.shared.global [%0], [%1], 16;" :: "r"(dst), "l"(src) : "memory")
#define CP_COMMIT()  asm volatile("cp.async.commit_group;" ::: "memory")
#define CP_WAIT(n)   asm volatile("cp.async.wait_group %0;" :: "n"(n) : "memory")

// -------- zero scratch + output (d_out is poisoned) --------
__global__ void k_zero(float* __restrict__ out) {
    int i = blockIdx.x * 256 + threadIdx.x;
    if (i < BB * NN) { g_msum[i] = 0.f; out[i] = 0.f; }
    g_score[i] = 0.f;
}

// -------- convert W_w to bf16 --------
__global__ void k_convW(const float* __restrict__ W) {
    int i = blockIdx.x * 256 + threadIdx.x;
    g_Wbf[i] = __float2bfloat16(W[i]);
}

// -------- mean over T (partials via atomics) + bf16 conversion of hyp --------
__global__ void k_mean(const float* __restrict__ hyp) {
    int b   = blockIdx.x;
    int tc  = blockIdx.y;
    int tid = threadIdx.x;
    float a0 = 0.f, a1 = 0.f, a2 = 0.f, a3 = 0.f;
    size_t base = ((size_t)tc * 128 * BB + b) * NN + (size_t)tid * 4;
    #pragma unroll 4
    for (int t = 0; t < 128; t++) {
        size_t off = base + (size_t)t * BB * NN;
        float4 v = *(const float4*)(hyp + off);
        a0 += v.x; a1 += v.y; a2 += v.z; a3 += v.w;
        __nv_bfloat162 lo = __floats2bfloat162_rn(v.x, v.y);
        __nv_bfloat162 hi = __floats2bfloat162_rn(v.z, v.w);
        uint2 u;
        u.x = *(uint32_t*)&lo;
        u.y = *(uint32_t*)&hi;
        *(uint2*)(g_Abf + off) = u;
    }
    int n0 = tid * 4;
    atomicAdd(&g_msum[b * NN + n0 + 0], a0);
    atomicAdd(&g_msum[b * NN + n0 + 1], a1);
    atomicAdd(&g_msum[b * NN + n0 + 2], a2);
    atomicAdd(&g_msum[b * NN + n0 + 3], a3);
}

// -------- g[b,q] = Wh_w[q] * tanh(mean . Wm_w[q] + Wm_b[q]) --------
__global__ void __launch_bounds__(256) k_g(const float* __restrict__ Wm_w,
                                           const float* __restrict__ Wm_b,
                                           const float* __restrict__ Wh_w) {
    const int b    = blockIdx.y;
    const int tid  = threadIdx.x;
    const int warp = tid >> 5, lane = tid & 31;
    const int q    = blockIdx.x * 8 + warp;

    __shared__ __align__(16) float m[NN];
    for (int i = tid; i < NN / 4; i += 256) {
        float4 v = *(const float4*)(g_msum + b * NN + i * 4);
        v.x *= (1.0f / (float)TT); v.y *= (1.0f / (float)TT);
        v.z *= (1.0f / (float)TT); v.w *= (1.0f / (float)TT);
        *(float4*)(m + i * 4) = v;
    }
    __syncthreads();

    const float4* w4 = (const float4*)(Wm_w + (size_t)q * NN);
    const float4* m4 = (const float4*)m;
    float a0 = 0.f, a1 = 0.f, a2 = 0.f, a3 = 0.f;
    #pragma unroll
    for (int j = 0; j < 8; j++) {
        float4 wv = w4[lane + 32 * j];
        float4 mv = m4[lane + 32 * j];
        a0 = fmaf(mv.x, wv.x, a0);
        a1 = fmaf(mv.y, wv.y, a1);
        a2 = fmaf(mv.z, wv.z, a2);
        a3 = fmaf(mv.w, wv.w, a3);
    }
    float acc = (a0 + a1) + (a2 + a3);
    #pragma unroll
    for (int o = 16; o > 0; o >>= 1) acc += __shfl_xor_sync(0xffffffffu, acc, o);
    if (lane == 0)
        g_gvec[b * QQ + q] = tanhf(acc + Wm_b[q]) * Wh_w[q];
}

// -------- big GEMM (bf16 mma.sync, 4-stage cp.async) + fused epilogue --------
#define BK 32
#define LDT 40                    // row stride in bf16 (80B, 16B-aligned)
#define NSTG (NN / BK)            // 32
#define STG_A (128 * LDT * 2)     // 10240 B
#define STG_BYTES (2 * STG_A)     // A + B = 20480 B
#define SMEM_DYN (4 * STG_BYTES)  // 81920 B

__global__ void __launch_bounds__(256) k_gemm(const float* __restrict__ Wbias) {
    extern __shared__ __align__(16) char sm[];
    const uint32_t su = smem_u32(sm);
    __shared__ float gsm[BB * 128];
    __shared__ float bsm[128];

    const int qc  = blockIdx.x;   // 0..3 : 128-wide chunk of N2
    const int mt  = blockIdx.y;   // 0..511 : 128-row tile of M=65536
    const int tid = threadIdx.x;
    const int warp = tid >> 5, lane = tid & 31;
    const int wm = (warp >> 1) * 32;   // warp row offset
    const int wq = (warp & 1) * 64;    // warp col offset

    for (int i = tid; i < BB * 128; i += 256)
        gsm[i] = g_gvec[(i >> 7) * QQ + qc * 128 + (i & 127)];
    if (tid < 128) bsm[tid] = Wbias[qc * 128 + tid];

    float acc[2][8][4];
    #pragma unroll
    for (int i = 0; i < 2; i++)
        #pragma unroll
        for (int j = 0; j < 8; j++)
            #pragma unroll
            for (int e = 0; e < 4; e++) acc[i][j][e] = 0.f;

    const char* Abase = (const char*)(g_Abf + (size_t)mt * 128 * NN);
    const char* Bbase = (const char*)(g_Wbf + (size_t)qc * 128 * NN);

    const int lrow = tid >> 1;            // 0..127 : tile row (2 thr/row)
    const int lseg = (tid & 1) * 2;       // seg pair: each thread does segs {s, s+1}

    // stage loader: A 128x32 + B 128x32 bf16 rows (64B data, 80B pitch)
    auto load_stage = [&](int s, int kb) {
        uint32_t sb = su + s * STG_BYTES;
        const char* Ag = Abase + kb * (BK * 2);
        const char* Bg = Bbase + kb * (BK * 2);
        uint32_t da = sb + lrow * (LDT * 2) + lseg * 16;
        const char* sa = Ag + (size_t)lrow * (NN * 2) + lseg * 16;
        CP_ASYNC16(da, sa);
        CP_ASYNC16(da + 16, sa + 16);
        uint32_t db = da + STG_A;
        const char* sb2 = Bg + (size_t)lrow * (NN * 2) + lseg * 16;
        CP_ASYNC16(db, sb2);
        CP_ASYNC16(db + 16, sb2 + 16);
        CP_COMMIT();
    };

    load_stage(0, 0);
    load_stage(1, 1);
    load_stage(2, 2);

    for (int kb = 0; kb < NSTG; kb++) {
        if (kb <= NSTG - 3)      CP_WAIT(2);
        else if (kb == NSTG - 2) CP_WAIT(1);
        else                     CP_WAIT(0);
        __syncthreads();

        const __nv_bfloat16* As = (const __nv_bfloat16*)(sm + (kb & 3) * STG_BYTES);
        const __nv_bfloat16* Bs = (const __nv_bfloat16*)(sm + (kb & 3) * STG_BYTES + STG_A);

        #pragma unroll
        for (int ks = 0; ks < 2; ks++) {
            int c = ks * 16 + (lane & 3) * 2;
            uint32_t a[2][4];
            #pragma unroll
            for (int i = 0; i < 2; i++) {
                int r = wm + i * 16 + (lane >> 2);
                a[i][0] = *(const uint32_t*)&As[r * LDT + c];
                a[i][1] = *(const uint32_t*)&As[(r + 8) * LDT + c];
                a[i][2] = *(const uint32_t*)&As[r * LDT + c + 8];
                a[i][3] = *(const uint32_t*)&As[(r + 8) * LDT + c + 8];
            }
            #pragma unroll
            for (int j = 0; j < 8; j++) {
                int q = wq + j * 8 + (lane >> 2);
                uint32_t b0 = *(const uint32_t*)&Bs[q * LDT + c];
                uint32_t b1 = *(const uint32_t*)&Bs[q * LDT + c + 8];
                #pragma unroll
                for (int i = 0; i < 2; i++) {
                    asm volatile(
                        "mma.sync.aligned.m16n8k16.row.col.f32.bf16.bf16.f32 "
                        "{%0,%1,%2,%3}, {%4,%5,%6,%7}, {%8,%9}, {%0,%1,%2,%3};\n"
                        : "+f"(acc[i][j][0]), "+f"(acc[i][j][1]),
                          "+f"(acc[i][j][2]), "+f"(acc[i][j][3])
                        : "r"(a[i][0]), "r"(a[i][1]), "r"(a[i][2]), "r"(a[i][3]),
                          "r"(b0), "r"(b1));
                }
            }
        }
        __syncthreads();
        if (kb + 3 < NSTG) load_stage((kb + 3) & 3, kb + 3);
    }

    // epilogue: score_partial[m] = sum_q tanh(z + bias) * g[b, q]
    int bidx[2][2], trow[2][2];
    #pragma unroll
    for (int i = 0; i < 2; i++)
        #pragma unroll
        for (int h = 0; h < 2; h++) {
            int m = mt * 128 + wm + i * 16 + h * 8 + (lane >> 2);
            bidx[i][h] = m & (BB - 1);
            trow[i][h] = m >> 5;
        }
    float rs[2][2] = {{0.f, 0.f}, {0.f, 0.f}};
    #pragma unroll
    for (int i = 0; i < 2; i++)
        #pragma unroll
        for (int j = 0; j < 8; j++) {
            int ql = wq + j * 8 + ((lane & 3) << 1);
            float bb0 = bsm[ql], bb1 = bsm[ql + 1];
            #pragma unroll
            for (int h = 0; h < 2; h++) {
                float t0 = fast_tanh(acc[i][j][2 * h + 0] + bb0);
                float t1 = fast_tanh(acc[i][j][2 * h + 1] + bb1);
                const float* gp = &gsm[(bidx[i][h] << 7) + ql];
                rs[i][h] += t0 * gp[0] + t1 * gp[1];
            }
        }
    #pragma unroll
    for (int i = 0; i < 2; i++)
        #pragma unroll
        for (int h = 0; h < 2; h++) {
            float v = rs[i][h];
            v += __shfl_xor_sync(0xffffffffu, v, 1);
            v += __shfl_xor_sync(0xffffffffu, v, 2);
            if ((lane & 3) == 0)
                atomicAdd(&g_score[bidx[i][h] * TT + trow[i][h]], v);
        }
}

// -------- softmax over T per b (in-place on g_score) --------
__global__ void k_softmax() {
    int b = blockIdx.x, tid = threadIdx.x;
    __shared__ float sh[TT];
    __shared__ float red[8];
    __shared__ float bcast;
    float mx = -1e30f;
    for (int i = tid; i < TT; i += 256) {
        float v = g_score[b * TT + i];
        sh[i] = v;
        mx = fmaxf(mx, v);
    }
    #pragma unroll
    for (int o = 16; o > 0; o >>= 1) mx = fmaxf(mx, __shfl_xor_sync(0xffffffffu, mx, o));
    if ((tid & 31) == 0) red[tid >> 5] = mx;
    __syncthreads();
    if (tid == 0) {
        float m2 = red[0];
        for (int i = 1; i < 8; i++) m2 = fmaxf(m2, red[i]);
        bcast = m2;
    }
    __syncthreads();
    mx = bcast;
    float s = 0.f;
    for (int i = tid; i < TT; i += 256) {
        float e = __expf(sh[i] - mx);
        sh[i] = e;
        s += e;
    }
    #pragma unroll
    for (int o = 16; o > 0; o >>= 1) s += __shfl_xor_sync(0xffffffffu, s, o);
    if ((tid & 31) == 0) red[tid >> 5] = s;
    __syncthreads();
    if (tid == 0) {
        float t = 0.f;
        for (int i = 0; i < 8; i++) t += red[i];
        bcast = 1.f / t;
    }
    __syncthreads();
    float inv = bcast;
    for (int i = tid; i < TT; i += 256) g_score[b * TT + i] = sh[i] * inv;
}

// -------- c[b,n] = sum_t a[b,t] * hyp[t,b,n] (partials via atomics) --------
__global__ void k_wsum(const float* __restrict__ hyp, float* __restrict__ out) {
    int b = blockIdx.x, tc = blockIdx.y, tid = threadIdx.x;
    __shared__ float aw[128];
    if (tid < 128) aw[tid] = g_score[b * TT + tc * 128 + tid];
    __syncthreads();
    float a0 = 0.f, a1 = 0.f, a2 = 0.f, a3 = 0.f;
    size_t base = ((size_t)tc * 128 * BB + b) * NN + (size_t)tid * 4;
    #pragma unroll 4
    for (int t = 0; t < 128; t++) {
        float w = aw[t];
        float4 v = *(const float4*)(hyp + base + (size_t)t * BB * NN);
        a0 = fmaf(w, v.x, a0);
        a1 = fmaf(w, v.y, a1);
        a2 = fmaf(w, v.z, a2);
        a3 = fmaf(w, v.w, a3);
    }
    int n0 = tid * 4;
    atomicAdd(&out[b * NN + n0 + 0], a0);
    atomicAdd(&out[b * NN + n0 + 1], a1);
    atomicAdd(&out[b * NN + n0 + 2], a2);
    atomicAdd(&out[b * NN + n0 + 3], a3);
}

extern "C" void kernel_launch(void* const* d_in, const int* in_sizes, int n_in,
                              void* d_out, int out_size) {
    (void)in_sizes; (void)n_in; (void)out_size;
    const float* hyp  = (const float*)d_in[0];
    const float* W_w  = (const float*)d_in[1];
    const float* W_b  = (const float*)d_in[2];
    const float* Wm_w = (const float*)d_in[3];
    const float* Wm_b = (const float*)d_in[4];
    const float* Wh_w = (const float*)d_in[5];
    float* out = (float*)d_out;

    cudaFuncSetAttribute(k_gemm, cudaFuncAttributeMaxDynamicSharedMemorySize, SMEM_DYN);

    k_zero<<<(BB * TT) / 256, 256>>>(out);
    k_convW<<<(QQ * NN) / 256, 256>>>(W_w);
    k_mean<<<dim3(BB, 16), 256>>>(hyp);
    k_g<<<dim3(QQ / 8, BB), 256>>>(Wm_w, Wm_b, Wh_w);
    k_gemm<<<dim3(4, 512), 256, SMEM_DYN>>>(W_b);
    k_softmax<<<BB, 256>>>();
    k_wsum<<<dim3(BB, 16), 256>>>(hyp, out);
}

// round 6
// speedup vs baseline: 1.8157x; 1.0755x over previous
#include <cuda_runtime.h>
#include <cuda_bf16.h>
#include <cstdint>

#define TT 2048
#define BB 32
#define NN 1024
#define QQ 512

// -------- scratch (device globals; no allocations allowed) --------
__device__ __nv_bfloat16 g_Abf[(size_t)TT * BB * NN];   // hyp in bf16, rows m=t*B+b
__device__ __nv_bfloat16 g_Wbf[QQ * NN];                // W_w in bf16 (row-major [q][k])
__device__ float g_msum[BB * NN];                       // sum over T (scaled later)
__device__ float g_gvec[BB * QQ];                       // g[b,q] = Wh[q]*tanh(m@Wm^T+bm)
__device__ float g_score[BB * TT];                      // scores, then attn weights

__device__ __forceinline__ float fast_tanh(float x) {
    float y;
    asm("tanh.approx.f32 %0, %1;" : "=f"(y) : "f"(x));
    return y;
}

__device__ __forceinline__ uint32_t smem_u32(const void* p) {
    uint32_t a;
    asm("{ .reg .u64 t; cvta.to.shared.u64 t, %1; cvt.u32.u64 %0, t; }" : "=r"(a) : "l"(p));
    return a;
}
#define CP_ASYNC16(dst, src) \
    asm volatile("cp.async.cg.shared.global [%0], [%1], 16;" :: "r"(dst), "l"(src) : "memory")
#define CP_COMMIT()  asm volatile("cp.async.commit_group;" ::: "memory")
#define CP_WAIT(n)   asm volatile("cp.async.wait_group %0;" :: "n"(n) : "memory")
#define LDSM_X4(r, a) \
    asm volatile("ldmatrix.sync.aligned.m8n8.x4.shared.b16 {%0,%1,%2,%3}, [%4];" \
        : "=r"((r)[0]), "=r"((r)[1]), "=r"((r)[2]), "=r"((r)[3]) : "r"(a))

// -------- zero scratch + output (d_out is poisoned) --------
__global__ void k_zero(float* __restrict__ out) {
    int i = blockIdx.x * 256 + threadIdx.x;
    if (i < BB * NN) { g_msum[i] = 0.f; out[i] = 0.f; }
    g_score[i] = 0.f;
}

// -------- convert W_w to bf16 --------
__global__ void k_convW(const float* __restrict__ W) {
    int i = blockIdx.x * 256 + threadIdx.x;
    g_Wbf[i] = __float2bfloat16(W[i]);
}

// -------- mean over T (partials via atomics) + bf16 conversion of hyp --------
__global__ void k_mean(const float* __restrict__ hyp) {
    int b   = blockIdx.x;
    int tc  = blockIdx.y;
    int tid = threadIdx.x;
    float a0 = 0.f, a1 = 0.f, a2 = 0.f, a3 = 0.f;
    size_t base = ((size_t)tc * 128 * BB + b) * NN + (size_t)tid * 4;
    #pragma unroll 4
    for (int t = 0; t < 128; t++) {
        size_t off = base + (size_t)t * BB * NN;
        float4 v = *(const float4*)(hyp + off);
        a0 += v.x; a1 += v.y; a2 += v.z; a3 += v.w;
        __nv_bfloat162 lo = __floats2bfloat162_rn(v.x, v.y);
        __nv_bfloat162 hi = __floats2bfloat162_rn(v.z, v.w);
        uint2 u;
        u.x = *(uint32_t*)&lo;
        u.y = *(uint32_t*)&hi;
        *(uint2*)(g_Abf + off) = u;
    }
    int n0 = tid * 4;
    atomicAdd(&g_msum[b * NN + n0 + 0], a0);
    atomicAdd(&g_msum[b * NN + n0 + 1], a1);
    atomicAdd(&g_msum[b * NN + n0 + 2], a2);
    atomicAdd(&g_msum[b * NN + n0 + 3], a3);
}

// -------- g[b,q] = Wh_w[q] * tanh(mean . Wm_w[q] + Wm_b[q]) --------
__global__ void __launch_bounds__(256) k_g(const float* __restrict__ Wm_w,
                                           const float* __restrict__ Wm_b,
                                           const float* __restrict__ Wh_w) {
    const int b    = blockIdx.y;
    const int tid  = threadIdx.x;
    const int warp = tid >> 5, lane = tid & 31;
    const int q    = blockIdx.x * 8 + warp;

    __shared__ __align__(16) float m[NN];
    for (int i = tid; i < NN / 4; i += 256) {
        float4 v = *(const float4*)(g_msum + b * NN + i * 4);
        v.x *= (1.0f / (float)TT); v.y *= (1.0f / (float)TT);
        v.z *= (1.0f / (float)TT); v.w *= (1.0f / (float)TT);
        *(float4*)(m + i * 4) = v;
    }
    __syncthreads();

    const float4* w4 = (const float4*)(Wm_w + (size_t)q * NN);
    const float4* m4 = (const float4*)m;
    float a0 = 0.f, a1 = 0.f, a2 = 0.f, a3 = 0.f;
    #pragma unroll
    for (int j = 0; j < 8; j++) {
        float4 wv = w4[lane + 32 * j];
        float4 mv = m4[lane + 32 * j];
        a0 = fmaf(mv.x, wv.x, a0);
        a1 = fmaf(mv.y, wv.y, a1);
        a2 = fmaf(mv.z, wv.z, a2);
        a3 = fmaf(mv.w, wv.w, a3);
    }
    float acc = (a0 + a1) + (a2 + a3);
    #pragma unroll
    for (int o = 16; o > 0; o >>= 1) acc += __shfl_xor_sync(0xffffffffu, acc, o);
    if (lane == 0)
        g_gvec[b * QQ + q] = tanhf(acc + Wm_b[q]) * Wh_w[q];
}

// -------- big GEMM (bf16 mma.sync + ldmatrix, 4-stage cp.async) --------
#define BK 32
#define LDT 40                    // row stride in bf16 (80B, 16B-aligned)
#define NSTG (NN / BK)            // 32
#define STG_A (128 * LDT * 2)     // 10240 B
#define STG_BYTES (2 * STG_A)     // A + B = 20480 B
#define SMEM_DYN (4 * STG_BYTES)  // 81920 B

__global__ void __launch_bounds__(256) k_gemm(const float* __restrict__ Wbias) {
    extern __shared__ __align__(16) char sm[];
    const uint32_t su = smem_u32(sm);
    __shared__ float gsm[BB * 128];
    __shared__ float bsm[128];

    const int qc  = blockIdx.x;   // 0..3 : 128-wide chunk of N2
    const int mt  = blockIdx.y;   // 0..511 : 128-row tile of M=65536
    const int tid = threadIdx.x;
    const int warp = tid >> 5, lane = tid & 31;
    const int wm = (warp >> 1) * 32;   // warp row offset
    const int wq = (warp & 1) * 64;    // warp col offset

    for (int i = tid; i < BB * 128; i += 256)
        gsm[i] = g_gvec[(i >> 7) * QQ + qc * 128 + (i & 127)];
    if (tid < 128) bsm[tid] = Wbias[qc * 128 + tid];

    float acc[2][8][4];
    #pragma unroll
    for (int i = 0; i < 2; i++)
        #pragma unroll
        for (int j = 0; j < 8; j++)
            #pragma unroll
            for (int e = 0; e < 4; e++) acc[i][j][e] = 0.f;

    const char* Abase = (const char*)(g_Abf + (size_t)mt * 128 * NN);
    const char* Bbase = (const char*)(g_Wbf + (size_t)qc * 128 * NN);

    const int lrow = tid >> 1;            // 0..127 : tile row (2 thr/row)
    const int lseg = (tid & 1) * 2;       // seg pair

    auto load_stage = [&](int s, int kb) {
        uint32_t sb = su + s * STG_BYTES;
        const char* Ag = Abase + kb * (BK * 2);
        const char* Bg = Bbase + kb * (BK * 2);
        uint32_t da = sb + lrow * (LDT * 2) + lseg * 16;
        const char* sa = Ag + (size_t)lrow * (NN * 2) + lseg * 16;
        CP_ASYNC16(da, sa);
        CP_ASYNC16(da + 16, sa + 16);
        uint32_t db = da + STG_A;
        const char* sb2 = Bg + (size_t)lrow * (NN * 2) + lseg * 16;
        CP_ASYNC16(db, sb2);
        CP_ASYNC16(db + 16, sb2 + 16);
        CP_COMMIT();
    };

    load_stage(0, 0);
    load_stage(1, 1);
    load_stage(2, 2);

    // ldmatrix per-lane row/col-half offsets
    const int aro = ((lane >> 3) & 1) * 8 + (lane & 7);   // A: m0/m1 = row halves
    const int akh = ((lane >> 4) & 1) * 8;                // A: m2/m3 = k halves
    const int bro = ((lane >> 4) & 1) * 8 + (lane & 7);   // B: m2/m3 = row halves
    const int bkh = ((lane >> 3) & 1) * 8;                // B: m1/m3 = k halves

    for (int kb = 0; kb < NSTG; kb++) {
        if (kb <= NSTG - 3)      CP_WAIT(2);
        else if (kb == NSTG - 2) CP_WAIT(1);
        else                     CP_WAIT(0);
        __syncthreads();
        if (kb + 3 < NSTG) load_stage((kb + 3) & 3, kb + 3);

        uint32_t sbase = su + (kb & 3) * STG_BYTES;
        #pragma unroll
        for (int ks = 0; ks < 2; ks++) {
            int kofs = ks * 16;
            uint32_t a[2][4];
            #pragma unroll
            for (int i = 0; i < 2; i++) {
                uint32_t addrA = sbase +
                    (uint32_t)((wm + i * 16 + aro) * LDT + kofs + akh) * 2;
                LDSM_X4(a[i], addrA);
            }
            #pragma unroll
            for (int jj = 0; jj < 4; jj++) {
                uint32_t bfr[4];
                uint32_t addrB = sbase + STG_A +
                    (uint32_t)((wq + jj * 16 + bro) * LDT + kofs + bkh) * 2;
                LDSM_X4(bfr, addrB);
                #pragma unroll
                for (int i = 0; i < 2; i++) {
                    asm volatile(
                        "mma.sync.aligned.m16n8k16.row.col.f32.bf16.bf16.f32 "
                        "{%0,%1,%2,%3}, {%4,%5,%6,%7}, {%8,%9}, {%0,%1,%2,%3};\n"
                        : "+f"(acc[i][2 * jj][0]), "+f"(acc[i][2 * jj][1]),
                          "+f"(acc[i][2 * jj][2]), "+f"(acc[i][2 * jj][3])
                        : "r"(a[i][0]), "r"(a[i][1]), "r"(a[i][2]), "r"(a[i][3]),
                          "r"(bfr[0]), "r"(bfr[1]));
                    asm volatile(
                        "mma.sync.aligned.m16n8k16.row.col.f32.bf16.bf16.f32 "
                        "{%0,%1,%2,%3}, {%4,%5,%6,%7}, {%8,%9}, {%0,%1,%2,%3};\n"
                        : "+f"(acc[i][2 * jj + 1][0]), "+f"(acc[i][2 * jj + 1][1]),
                          "+f"(acc[i][2 * jj + 1][2]), "+f"(acc[i][2 * jj + 1][3])
                        : "r"(a[i][0]), "r"(a[i][1]), "r"(a[i][2]), "r"(a[i][3]),
                          "r"(bfr[2]), "r"(bfr[3]));
                }
            }
        }
    }

    // epilogue: score_partial[m] = sum_q tanh(z + bias) * g[b, q]
    int bidx[2][2], trow[2][2];
    #pragma unroll
    for (int i = 0; i < 2; i++)
        #pragma unroll
        for (int h = 0; h < 2; h++) {
            int m = mt * 128 + wm + i * 16 + h * 8 + (lane >> 2);
            bidx[i][h] = m & (BB - 1);
            trow[i][h] = m >> 5;
        }
    float rs[2][2] = {{0.f, 0.f}, {0.f, 0.f}};
    #pragma unroll
    for (int i = 0; i < 2; i++)
        #pragma unroll
        for (int j = 0; j < 8; j++) {
            int ql = wq + j * 8 + ((lane & 3) << 1);
            float bb0 = bsm[ql], bb1 = bsm[ql + 1];
            #pragma unroll
            for (int h = 0; h < 2; h++) {
                float t0 = fast_tanh(acc[i][j][2 * h + 0] + bb0);
                float t1 = fast_tanh(acc[i][j][2 * h + 1] + bb1);
                const float* gp = &gsm[(bidx[i][h] << 7) + ql];
                rs[i][h] += t0 * gp[0] + t1 * gp[1];
            }
        }
    #pragma unroll
    for (int i = 0; i < 2; i++)
        #pragma unroll
        for (int h = 0; h < 2; h++) {
            float v = rs[i][h];
            v += __shfl_xor_sync(0xffffffffu, v, 1);
            v += __shfl_xor_sync(0xffffffffu, v, 2);
            if ((lane & 3) == 0)
                atomicAdd(&g_score[bidx[i][h] * TT + trow[i][h]], v);
        }
}

// -------- softmax over T per b (in-place on g_score) --------
__global__ void k_softmax() {
    int b = blockIdx.x, tid = threadIdx.x;
    __shared__ float sh[TT];
    __shared__ float red[8];
    __shared__ float bcast;
    float mx = -1e30f;
    for (int i = tid; i < TT; i += 256) {
        float v = g_score[b * TT + i];
        sh[i] = v;
        mx = fmaxf(mx, v);
    }
    #pragma unroll
    for (int o = 16; o > 0; o >>= 1) mx = fmaxf(mx, __shfl_xor_sync(0xffffffffu, mx, o));
    if ((tid & 31) == 0) red[tid >> 5] = mx;
    __syncthreads();
    if (tid == 0) {
        float m2 = red[0];
        for (int i = 1; i < 8; i++) m2 = fmaxf(m2, red[i]);
        bcast = m2;
    }
    __syncthreads();
    mx = bcast;
    float s = 0.f;
    for (int i = tid; i < TT; i += 256) {
        float e = __expf(sh[i] - mx);
        sh[i] = e;
        s += e;
    }
    #pragma unroll
    for (int o = 16; o > 0; o >>= 1) s += __shfl_xor_sync(0xffffffffu, s, o);
    if ((tid & 31) == 0) red[tid >> 5] = s;
    __syncthreads();
    if (tid == 0) {
        float t = 0.f;
        for (int i = 0; i < 8; i++) t += red[i];
        bcast = 1.f / t;
    }
    __syncthreads();
    float inv = bcast;
    for (int i = tid; i < TT; i += 256) g_score[b * TT + i] = sh[i] * inv;
}

// -------- c[b,n] = sum_t a[b,t] * hyp[t,b,n] (partials via atomics) --------
__global__ void k_wsum(const float* __restrict__ hyp, float* __restrict__ out) {
    int b = blockIdx.x, tc = blockIdx.y, tid = threadIdx.x;
    __shared__ float aw[128];
    if (tid < 128) aw[tid] = g_score[b * TT + tc * 128 + tid];
    __syncthreads();
    float a0 = 0.f, a1 = 0.f, a2 = 0.f, a3 = 0.f;
    size_t base = ((size_t)tc * 128 * BB + b) * NN + (size_t)tid * 4;
    #pragma unroll 4
    for (int t = 0; t < 128; t++) {
        float w = aw[t];
        float4 v = *(const float4*)(hyp + base + (size_t)t * BB * NN);
        a0 = fmaf(w, v.x, a0);
        a1 = fmaf(w, v.y, a1);
        a2 = fmaf(w, v.z, a2);
        a3 = fmaf(w, v.w, a3);
    }
    int n0 = tid * 4;
    atomicAdd(&out[b * NN + n0 + 0], a0);
    atomicAdd(&out[b * NN + n0 + 1], a1);
    atomicAdd(&out[b * NN + n0 + 2], a2);
    atomicAdd(&out[b * NN + n0 + 3], a3);
}

extern "C" void kernel_launch(void* const* d_in, const int* in_sizes, int n_in,
                              void* d_out, int out_size) {
    (void)in_sizes; (void)n_in; (void)out_size;
    const float* hyp  = (const float*)d_in[0];
    const float* W_w  = (const float*)d_in[1];
    const float* W_b  = (const float*)d_in[2];
    const float* Wm_w = (const float*)d_in[3];
    const float* Wm_b = (const float*)d_in[4];
    const float* Wh_w = (const float*)d_in[5];
    float* out = (float*)d_out;

    cudaFuncSetAttribute(k_gemm, cudaFuncAttributeMaxDynamicSharedMemorySize, SMEM_DYN);

    k_zero<<<(BB * TT) / 256, 256>>>(out);
    k_convW<<<(QQ * NN) / 256, 256>>>(W_w);
    k_mean<<<dim3(BB, 16), 256>>>(hyp);
    k_g<<<dim3(QQ / 8, BB), 256>>>(Wm_w, Wm_b, Wh_w);
    k_gemm<<<dim3(4, 512), 256, SMEM_DYN>>>(W_b);
    k_softmax<<<BB, 256>>>();
    k_wsum<<<dim3(BB, 16), 256>>>(hyp, out);
}

// round 9
// speedup vs baseline: 2.4602x; 1.3549x over previous
#include <cuda_runtime.h>
#include <cuda.h>
#include <cuda_bf16.h>
#include <cstdint>

#define TT 2048
#define BB 32
#define NN 1024
#define QQ 512

// -------- scratch (device globals; no allocations allowed) --------
__device__ __align__(1024) __nv_bfloat16 g_Abf[(size_t)TT * BB * NN]; // hyp bf16, rows m=t*B+b
__device__ __align__(1024) __nv_bfloat16 g_Wbf[QQ * NN];              // W_w bf16 [q][k]
__device__ float g_msum[BB * NN];
__device__ float g_gvec[BB * QQ];
__device__ float g_score[BB * TT];

__device__ __forceinline__ float fast_tanh(float x) {
    float y;
    asm("tanh.approx.f32 %0, %1;" : "=f"(y) : "f"(x));
    return y;
}
__device__ __forceinline__ uint32_t smem_u32(const void* p) {
    uint32_t a;
    asm("{ .reg .u64 t; cvta.to.shared.u64 t, %1; cvt.u32.u64 %0, t; }" : "=r"(a) : "l"(p));
    return a;
}
#define LDSM_X4(r, a) \
    asm volatile("ldmatrix.sync.aligned.m8n8.x4.shared.b16 {%0,%1,%2,%3}, [%4];" \
        : "=r"((r)[0]), "=r"((r)[1]), "=r"((r)[2]), "=r"((r)[3]) : "r"(a))
#define MBAR_INIT(a, c) asm volatile("mbarrier.init.shared.b64 [%0], %1;" :: "r"(a), "r"(c) : "memory")
#define MBAR_EXPECT_TX(a, n) \
    asm volatile("mbarrier.arrive.expect_tx.shared.b64 _, [%0], %1;" :: "r"(a), "r"(n) : "memory")
// proven acquire try_wait loop form (ptx_helpers MBARRIER_WAIT_PARITY)
#define MBAR_WAIT(a, ph) do { \
    asm volatile("{\n\t.reg .pred P1;\n\tWL_%=:\n\t" \
        "mbarrier.try_wait.parity.acquire.cta.shared::cta.b64 P1, [%0], %1, 0x989680;\n\t" \
        "@P1 bra.uni WD_%=;\n\tbra.uni WL_%=;\n\tWD_%=:\n\t}" \
        :: "r"(a), "r"(ph) : "memory"); } while (0)
// proven non-cluster TMA form (ptx_helpers tma_load_2d): shared::cta dst
#define TMA_LOAD_2D(smaddr, map, c0, c1, mb) \
    asm volatile("cp.async.bulk.tensor.2d.shared::cta.global.tile.mbarrier::complete_tx::bytes " \
        "[%0], [%1, {%2, %3}], [%4];" \
        :: "r"(smaddr), "l"(map), "r"(c0), "r"(c1), "r"(mb) : "memory")

// -------- zero scratch + output --------
__global__ void k_zero(float* __restrict__ out) {
    int i = blockIdx.x * 256 + threadIdx.x;
    if (i < BB * NN) { g_msum[i] = 0.f; out[i] = 0.f; }
    g_score[i] = 0.f;
}

// -------- convert W_w to bf16 --------
__global__ void k_convW(const float* __restrict__ W) {
    int i = blockIdx.x * 256 + threadIdx.x;
    g_Wbf[i] = __float2bfloat16(W[i]);
}

// -------- mean over T (atomics) + bf16 conversion of hyp --------
__global__ void k_mean(const float* __restrict__ hyp) {
    int b   = blockIdx.x;
    int tc  = blockIdx.y;
    int tid = threadIdx.x;
    float a0 = 0.f, a1 = 0.f, a2 = 0.f, a3 = 0.f;
    size_t base = ((size_t)tc * 128 * BB + b) * NN + (size_t)tid * 4;
    #pragma unroll 4
    for (int t = 0; t < 128; t++) {
        size_t off = base + (size_t)t * BB * NN;
        float4 v = *(const float4*)(hyp + off);
        a0 += v.x; a1 += v.y; a2 += v.z; a3 += v.w;
        __nv_bfloat162 lo = __floats2bfloat162_rn(v.x, v.y);
        __nv_bfloat162 hi = __floats2bfloat162_rn(v.z, v.w);
        uint2 u;
        u.x = *(uint32_t*)&lo;
        u.y = *(uint32_t*)&hi;
        *(uint2*)(g_Abf + off) = u;
    }
    int n0 = tid * 4;
    atomicAdd(&g_msum[b * NN + n0 + 0], a0);
    atomicAdd(&g_msum[b * NN + n0 + 1], a1);
    atomicAdd(&g_msum[b * NN + n0 + 2], a2);
    atomicAdd(&g_msum[b * NN + n0 + 3], a3);
}

// -------- g[b,q] --------
__global__ void __launch_bounds__(256) k_g(const float* __restrict__ Wm_w,
                                           const float* __restrict__ Wm_b,
                                           const float* __restrict__ Wh_w) {
    const int b    = blockIdx.y;
    const int tid  = threadIdx.x;
    const int warp = tid >> 5, lane = tid & 31;
    const int q    = blockIdx.x * 8 + warp;

    __shared__ __align__(16) float m[NN];
    for (int i = tid; i < NN / 4; i += 256) {
        float4 v = *(const float4*)(g_msum + b * NN + i * 4);
        v.x *= (1.0f / (float)TT); v.y *= (1.0f / (float)TT);
        v.z *= (1.0f / (float)TT); v.w *= (1.0f / (float)TT);
        *(float4*)(m + i * 4) = v;
    }
    __syncthreads();

    const float4* w4 = (const float4*)(Wm_w + (size_t)q * NN);
    const float4* m4 = (const float4*)m;
    float a0 = 0.f, a1 = 0.f, a2 = 0.f, a3 = 0.f;
    #pragma unroll
    for (int j = 0; j < 8; j++) {
        float4 wv = w4[lane + 32 * j];
        float4 mv = m4[lane + 32 * j];
        a0 = fmaf(mv.x, wv.x, a0);
        a1 = fmaf(mv.y, wv.y, a1);
        a2 = fmaf(mv.z, wv.z, a2);
        a3 = fmaf(mv.w, wv.w, a3);
    }
    float acc = (a0 + a1) + (a2 + a3);
    #pragma unroll
    for (int o = 16; o > 0; o >>= 1) acc += __shfl_xor_sync(0xffffffffu, acc, o);
    if (lane == 0)
        g_gvec[b * QQ + q] = tanhf(acc + Wm_b[q]) * Wh_w[q];
}

// -------- big GEMM: TMA-fed, bf16 mma.sync + ldmatrix, 3-stage ring --------
#define BK 64
#define NSTG (NN / BK)            // 16
#define STG_A 16384               // 128 rows x 128B
#define STG_BYTES 32768           // A + B
#define SMEM_DYN (3 * STG_BYTES)  // 98304

__global__ void __launch_bounds__(256) k_gemm(const float* __restrict__ Wbias,
                                              const __grid_constant__ CUtensorMap tmA,
                                              const __grid_constant__ CUtensorMap tmB) {
    extern __shared__ __align__(1024) char sm[];
    __shared__ __align__(8) uint64_t mbar[3];
    const uint32_t su = smem_u32(sm);

    const int qc  = blockIdx.x;   // 0..3 : 128-wide chunk of N2
    const int mt  = blockIdx.y;   // 0..511 : 128-row tile of M
    const int tid = threadIdx.x;
    const int warp = tid >> 5, lane = tid & 31;
    const int wm = (warp >> 1) * 32;
    const int wq = (warp & 1) * 64;

    if (tid == 0) {
        #pragma unroll
        for (int s = 0; s < 3; s++) MBAR_INIT(smem_u32(&mbar[s]), 1);
        asm volatile("fence.proxy.async.shared::cta;" ::: "memory");
    }
    __syncthreads();
    if (tid == 0) {
        #pragma unroll
        for (int s = 0; s < 3; s++) {
            uint32_t mb = smem_u32(&mbar[s]);
            MBAR_EXPECT_TX(mb, STG_BYTES);
            TMA_LOAD_2D(su + s * STG_BYTES, &tmA, s * BK, mt * 128, mb);
            TMA_LOAD_2D(su + s * STG_BYTES + STG_A, &tmB, s * BK, qc * 128, mb);
        }
    }

    float acc[2][8][4];
    #pragma unroll
    for (int i = 0; i < 2; i++)
        #pragma unroll
        for (int j = 0; j < 8; j++)
            #pragma unroll
            for (int e = 0; e < 4; e++) acc[i][j][e] = 0.f;

    // ldmatrix per-lane row/col-half offsets
    const int aro = ((lane >> 3) & 1) * 8 + (lane & 7);
    const int akh = ((lane >> 4) & 1) * 8;
    const int bro = ((lane >> 4) & 1) * 8 + (lane & 7);
    const int bkh = ((lane >> 3) & 1) * 8;

    for (int kb = 0; kb < NSTG; kb++) {
        int s = kb % 3;
        MBAR_WAIT(smem_u32(&mbar[s]), (kb / 3) & 1);

        uint32_t sa = su + s * STG_BYTES;
        uint32_t sb = sa + STG_A;
        #pragma unroll
        for (int ks = 0; ks < 4; ks++) {
            uint32_t a[2][4];
            #pragma unroll
            for (int i = 0; i < 2; i++) {
                int row = wm + i * 16 + aro;
                uint32_t colb = (uint32_t)(ks * 16 + akh) * 2;
                uint32_t addrA = sa + row * 128 + (colb ^ ((row & 7) << 4));
                LDSM_X4(a[i], addrA);
            }
            #pragma unroll
            for (int jj = 0; jj < 4; jj++) {
                uint32_t bfr[4];
                int row = wq + jj * 16 + bro;
                uint32_t colb = (uint32_t)(ks * 16 + bkh) * 2;
                uint32_t addrB = sb + row * 128 + (colb ^ ((row & 7) << 4));
                LDSM_X4(bfr, addrB);
                #pragma unroll
                for (int i = 0; i < 2; i++) {
                    asm volatile(
                        "mma.sync.aligned.m16n8k16.row.col.f32.bf16.bf16.f32 "
                        "{%0,%1,%2,%3}, {%4,%5,%6,%7}, {%8,%9}, {%0,%1,%2,%3};\n"
                        : "+f"(acc[i][2 * jj][0]), "+f"(acc[i][2 * jj][1]),
                          "+f"(acc[i][2 * jj][2]), "+f"(acc[i][2 * jj][3])
                        : "r"(a[i][0]), "r"(a[i][1]), "r"(a[i][2]), "r"(a[i][3]),
                          "r"(bfr[0]), "r"(bfr[1]));
                    asm volatile(
                        "mma.sync.aligned.m16n8k16.row.col.f32.bf16.bf16.f32 "
                        "{%0,%1,%2,%3}, {%4,%5,%6,%7}, {%8,%9}, {%0,%1,%2,%3};\n"
                        : "+f"(acc[i][2 * jj + 1][0]), "+f"(acc[i][2 * jj + 1][1]),
                          "+f"(acc[i][2 * jj + 1][2]), "+f"(acc[i][2 * jj + 1][3])
                        : "r"(a[i][0]), "r"(a[i][1]), "r"(a[i][2]), "r"(a[i][3]),
                          "r"(bfr[2]), "r"(bfr[3]));
                }
            }
        }
        __syncthreads();   // slot s fully consumed by whole CTA
        if (tid == 0 && kb + 3 < NSTG) {
            uint32_t mb = smem_u32(&mbar[s]);
            MBAR_EXPECT_TX(mb, STG_BYTES);
            TMA_LOAD_2D(su + s * STG_BYTES, &tmA, (kb + 3) * BK, mt * 128, mb);
            TMA_LOAD_2D(su + s * STG_BYTES + STG_A, &tmB, (kb + 3) * BK, qc * 128, mb);
        }
    }

    // ---- stage g + bias into (now dead) stage buffers ----
    float* gsm = (float*)sm;                 // [BB][128]
    float* bsm = (float*)(sm + 16384);       // [128]
    for (int i = tid; i < BB * 128; i += 256)
        gsm[i] = g_gvec[(i >> 7) * QQ + qc * 128 + (i & 127)];
    if (tid < 128) bsm[tid] = Wbias[qc * 128 + tid];
    __syncthreads();

    // ---- epilogue: score_partial[m] = sum_q tanh(z + bias) * g[b, q] ----
    int bidx[2][2], trow[2][2];
    #pragma unroll
    for (int i = 0; i < 2; i++)
        #pragma unroll
        for (int h = 0; h < 2; h++) {
            int m = mt * 128 + wm + i * 16 + h * 8 + (lane >> 2);
            bidx[i][h] = m & (BB - 1);
            trow[i][h] = m >> 5;
        }
    float rs[2][2] = {{0.f, 0.f}, {0.f, 0.f}};
    #pragma unroll
    for (int i = 0; i < 2; i++)
        #pragma unroll
        for (int j = 0; j < 8; j++) {
            int ql = wq + j * 8 + ((lane & 3) << 1);
            float bb0 = bsm[ql], bb1 = bsm[ql + 1];
            #pragma unroll
            for (int h = 0; h < 2; h++) {
                float t0 = fast_tanh(acc[i][j][2 * h + 0] + bb0);
                float t1 = fast_tanh(acc[i][j][2 * h + 1] + bb1);
                const float* gp = &gsm[(bidx[i][h] << 7) + ql];
                rs[i][h] += t0 * gp[0] + t1 * gp[1];
            }
        }
    #pragma unroll
    for (int i = 0; i < 2; i++)
        #pragma unroll
        for (int h = 0; h < 2; h++) {
            float v = rs[i][h];
            v += __shfl_xor_sync(0xffffffffu, v, 1);
            v += __shfl_xor_sync(0xffffffffu, v, 2);
            if ((lane & 3) == 0)
                atomicAdd(&g_score[bidx[i][h] * TT + trow[i][h]], v);
        }
}

// -------- softmax over T per b --------
__global__ void k_softmax() {
    int b = blockIdx.x, tid = threadIdx.x;
    __shared__ float sh[TT];
    __shared__ float red[8];
    __shared__ float bcast;
    float mx = -1e30f;
    for (int i = tid; i < TT; i += 256) {
        float v = g_score[b * TT + i];
        sh[i] = v;
        mx = fmaxf(mx, v);
    }
    #pragma unroll
    for (int o = 16; o > 0; o >>= 1) mx = fmaxf(mx, __shfl_xor_sync(0xffffffffu, mx, o));
    if ((tid & 31) == 0) red[tid >> 5] = mx;
    __syncthreads();
    if (tid == 0) {
        float m2 = red[0];
        for (int i = 1; i < 8; i++) m2 = fmaxf(m2, red[i]);
        bcast = m2;
    }
    __syncthreads();
    mx = bcast;
    float s = 0.f;
    for (int i = tid; i < TT; i += 256) {
        float e = __expf(sh[i] - mx);
        sh[i] = e;
        s += e;
    }
    #pragma unroll
    for (int o = 16; o > 0; o >>= 1) s += __shfl_xor_sync(0xffffffffu, s, o);
    if ((tid & 31) == 0) red[tid >> 5] = s;
    __syncthreads();
    if (tid == 0) {
        float t = 0.f;
        for (int i = 0; i < 8; i++) t += red[i];
        bcast = 1.f / t;
    }
    __syncthreads();
    float inv = bcast;
    for (int i = tid; i < TT; i += 256) g_score[b * TT + i] = sh[i] * inv;
}

// -------- c[b,n] = sum_t a[b,t] * hyp[t,b,n] --------
__global__ void k_wsum(const float* __restrict__ hyp, float* __restrict__ out) {
    int b = blockIdx.x, tc = blockIdx.y, tid = threadIdx.x;
    __shared__ float aw[128];
    if (tid < 128) aw[tid] = g_score[b * TT + tc * 128 + tid];
    __syncthreads();
    float a0 = 0.f, a1 = 0.f, a2 = 0.f, a3 = 0.f;
    size_t base = ((size_t)tc * 128 * BB + b) * NN + (size_t)tid * 4;
    #pragma unroll 4
    for (int t = 0; t < 128; t++) {
        float w = aw[t];
        float4 v = *(const float4*)(hyp + base + (size_t)t * BB * NN);
        a0 = fmaf(w, v.x, a0);
        a1 = fmaf(w, v.y, a1);
        a2 = fmaf(w, v.z, a2);
        a3 = fmaf(w, v.w, a3);
    }
    int n0 = tid * 4;
    atomicAdd(&out[b * NN + n0 + 0], a0);
    atomicAdd(&out[b * NN + n0 + 1], a1);
    atomicAdd(&out[b * NN + n0 + 2], a2);
    atomicAdd(&out[b * NN + n0 + 3], a3);
}

typedef CUresult (*PFN_tmEncode)(CUtensorMap*, CUtensorMapDataType, cuuint32_t, void*,
                                 const cuuint64_t*, const cuuint64_t*, const cuuint32_t*,
                                 const cuuint32_t*, CUtensorMapInterleave, CUtensorMapSwizzle,
                                 CUtensorMapL2promotion, CUtensorMapFloatOOBfill);

extern "C" void kernel_launch(void* const* d_in, const int* in_sizes, int n_in,
                              void* d_out, int out_size) {
    (void)in_sizes; (void)n_in; (void)out_size;
    const float* hyp  = (const float*)d_in[0];
    const float* W_w  = (const float*)d_in[1];
    const float* W_b  = (const float*)d_in[2];
    const float* Wm_w = (const float*)d_in[3];
    const float* Wm_b = (const float*)d_in[4];
    const float* Wh_w = (const float*)d_in[5];
    float* out = (float*)d_out;

    // Build tensor maps for the TMA-fed GEMM (driver entry point; no -lcuda link)
    void* fn = nullptr;
    cudaDriverEntryPointQueryResult qr;
    cudaGetDriverEntryPoint("cuTensorMapEncodeTiled", &fn, cudaEnableDefault, &qr);
    PFN_tmEncode enc = (PFN_tmEncode)fn;

    void *aptr = nullptr, *bptr = nullptr;
    cudaGetSymbolAddress(&aptr, g_Abf);
    cudaGetSymbolAddress(&bptr, g_Wbf);

    CUtensorMap tmA{}, tmB{};
    {
        cuuint64_t dims[2]    = {NN, (cuuint64_t)TT * BB};
        cuuint64_t strides[1] = {NN * 2};
        cuuint32_t box[2]     = {BK, 128};
        cuuint32_t es[2]      = {1, 1};
        enc(&tmA, CU_TENSOR_MAP_DATA_TYPE_BFLOAT16, 2, aptr, dims, strides, box, es,
            CU_TENSOR_MAP_INTERLEAVE_NONE, CU_TENSOR_MAP_SWIZZLE_128B,
            CU_TENSOR_MAP_L2_PROMOTION_L2_128B, CU_TENSOR_MAP_FLOAT_OOB_FILL_NONE);
    }
    {
        cuuint64_t dims[2]    = {NN, QQ};
        cuuint64_t strides[1] = {NN * 2};
        cuuint32_t box[2]     = {BK, 128};
        cuuint32_t es[2]      = {1, 1};
        enc(&tmB, CU_TENSOR_MAP_DATA_TYPE_BFLOAT16, 2, bptr, dims, strides, box, es,
            CU_TENSOR_MAP_INTERLEAVE_NONE, CU_TENSOR_MAP_SWIZZLE_128B,
            CU_TENSOR_MAP_L2_PROMOTION_L2_128B, CU_TENSOR_MAP_FLOAT_OOB_FILL_NONE);
    }

    cudaFuncSetAttribute(k_gemm, cudaFuncAttributeMaxDynamicSharedMemorySize, SMEM_DYN);

    k_zero<<<(BB * TT) / 256, 256>>>(out);
    k_convW<<<(QQ * NN) / 256, 256>>>(W_w);
    k_mean<<<dim3(BB, 16), 256>>>(hyp);
    k_g<<<dim3(QQ / 8, BB), 256>>>(Wm_w, Wm_b, Wh_w);
    k_gemm<<<dim3(4, 512), 256, SMEM_DYN>>>(W_b, tmA, tmB);
    k_softmax<<<BB, 256>>>();
    k_wsum<<<dim3(BB, 16), 256>>>(hyp, out);
}